// round 3
// baseline (speedup 1.0000x reference)
#include <cuda_runtime.h>

#define N_NODES 50000
#define N_EDGES 800000

// Scratch (allocation-free: __device__ globals, referenced directly in device code)
__device__ float g_h[N_NODES * 128];     // GEMM output per layer
__device__ float g_agg[N_NODES * 128];   // aggregation output (layers 1,2)
__device__ int   g_deg[N_NODES];
__device__ float g_dinv[N_NODES];

// ---------------- degree / normalization ----------------

__global__ void deg_init_kernel() {
    int i = blockIdx.x * blockDim.x + threadIdx.x;
    if (i < N_NODES) g_deg[i] = 1;  // self loop counts 1
}

__global__ void deg_count_kernel(const int* __restrict__ dst) {
    int i = blockIdx.x * blockDim.x + threadIdx.x;
    if (i < N_EDGES) atomicAdd(&g_deg[dst[i]], 1);
}

__global__ void dinv_kernel() {
    int i = blockIdx.x * blockDim.x + threadIdx.x;
    if (i < N_NODES) g_dinv[i] = rsqrtf((float)g_deg[i]);
}

// ---------------- dense GEMM: g_h[M,N] = act(X[M,128]) @ W[128,N] ----------------
// FROM_AGG: read from g_agg instead of the X parameter.

template<int N, bool RELU, bool FROM_AGG>
__global__ void gemm_kernel(const float* __restrict__ X, const float* __restrict__ W, int M) {
    constexpr int BM = 64, BK = 32, K = 128;
    constexpr int CG = N / 8;            // column groups of 8
    constexpr int TM = BM * CG / 256;    // rows per thread (4 for N=128, 2 for N=64)

    __shared__ float Xs[BM][BK + 4];
    __shared__ float Ws[BK][N];

    const float* __restrict__ Xp = FROM_AGG ? (const float*)g_agg : X;
    float* __restrict__ Y = (float*)g_h;

    const int tid = threadIdx.x;
    const int tx = tid % CG;             // column group
    const int ty = tid / CG;             // row group
    const int m0 = blockIdx.x * BM;

    float acc[TM][8];
#pragma unroll
    for (int r = 0; r < TM; r++)
#pragma unroll
        for (int c = 0; c < 8; c++) acc[r][c] = 0.0f;

#pragma unroll
    for (int kb = 0; kb < K / BK; kb++) {
        // Load X tile: BM x BK floats = 512 float4, 2 per thread
#pragma unroll
        for (int i = 0; i < 2; i++) {
            int idx = tid + i * 256;
            int row = idx >> 3;
            int kk = (idx & 7) * 4;
            int gm = m0 + row;
            float4 v = make_float4(0.f, 0.f, 0.f, 0.f);
            if (gm < M) v = *(const float4*)&Xp[(size_t)gm * K + kb * BK + kk];
            if (RELU) {
                v.x = fmaxf(v.x, 0.f); v.y = fmaxf(v.y, 0.f);
                v.z = fmaxf(v.z, 0.f); v.w = fmaxf(v.w, 0.f);
            }
            *(float4*)&Xs[row][kk] = v;
        }
        // Load W tile: BK x N floats
        constexpr int WF4 = BK * N / 4;      // 1024 (N=128) or 512 (N=64)
#pragma unroll
        for (int i = 0; i < WF4 / 256; i++) {
            int idx = tid + i * 256;
            int row = idx / (N / 4);
            int c = (idx % (N / 4)) * 4;
            *(float4*)&Ws[row][c] = *(const float4*)&W[(size_t)(kb * BK + row) * N + c];
        }
        __syncthreads();

#pragma unroll
        for (int k = 0; k < BK; k++) {
            float4 w0 = *(float4*)&Ws[k][tx * 8];
            float4 w1 = *(float4*)&Ws[k][tx * 8 + 4];
#pragma unroll
            for (int r = 0; r < TM; r++) {
                float xv = Xs[ty * TM + r][k];
                acc[r][0] += xv * w0.x; acc[r][1] += xv * w0.y;
                acc[r][2] += xv * w0.z; acc[r][3] += xv * w0.w;
                acc[r][4] += xv * w1.x; acc[r][5] += xv * w1.y;
                acc[r][6] += xv * w1.z; acc[r][7] += xv * w1.w;
            }
        }
        __syncthreads();
    }

#pragma unroll
    for (int r = 0; r < TM; r++) {
        int gm = m0 + ty * TM + r;
        if (gm < M) {
            float4 o0 = make_float4(acc[r][0], acc[r][1], acc[r][2], acc[r][3]);
            float4 o1 = make_float4(acc[r][4], acc[r][5], acc[r][6], acc[r][7]);
            *(float4*)&Y[(size_t)gm * N + tx * 8] = o0;
            *(float4*)&Y[(size_t)gm * N + tx * 8 + 4] = o1;
        }
    }
}

// ---------------- self-loop + bias init: dst[i] = g_h[i]*dinv[i]^2 + b ----------------
// TO_OUT: write to the `out` parameter (d_out) instead of g_agg.

template<int N, bool TO_OUT>
__global__ void init_agg_kernel(const float* __restrict__ b, float* __restrict__ out) {
    int idx4 = blockIdx.x * blockDim.x + threadIdx.x;
    constexpr int TOTAL4 = N_NODES * N / 4;
    if (idx4 >= TOTAL4) return;
    float* __restrict__ o = TO_OUT ? out : (float*)g_agg;
    int i = idx4 / (N / 4);
    int c = (idx4 % (N / 4)) * 4;
    float s = g_dinv[i];
    s *= s;
    float4 v = *(const float4*)&g_h[(size_t)i * N + c];
    v.x = v.x * s + b[c];
    v.y = v.y * s + b[c + 1];
    v.z = v.z * s + b[c + 2];
    v.w = v.w * s + b[c + 3];
    *(float4*)&o[(size_t)i * N + c] = v;
}

// ---------------- edge scatter: o[dst] += g_h[src] * dinv[src]*dinv[dst] ----------------

template<int N, bool TO_OUT>
__global__ void scatter_kernel(const int* __restrict__ src,
                               const int* __restrict__ dst,
                               float* __restrict__ out) {
    int gid = blockIdx.x * blockDim.x + threadIdx.x;
    int e = gid >> 5;
    int lane = gid & 31;
    if (e >= N_EDGES) return;
    float* __restrict__ o = TO_OUT ? out : (float*)g_agg;
    int s = src[e];
    int d = dst[e];
    float nrm = g_dinv[s] * g_dinv[d];
    if (N == 128) {
        float4 v = *(const float4*)&g_h[(size_t)s * N + lane * 4];
        float* op = &o[(size_t)d * N + lane * 4];
        atomicAdd(op + 0, v.x * nrm);
        atomicAdd(op + 1, v.y * nrm);
        atomicAdd(op + 2, v.z * nrm);
        atomicAdd(op + 3, v.w * nrm);
    } else {
        float2 v = *(const float2*)&g_h[(size_t)s * N + lane * 2];
        float* op = &o[(size_t)d * N + lane * 2];
        atomicAdd(op + 0, v.x * nrm);
        atomicAdd(op + 1, v.y * nrm);
    }
}

// ---------------- launch ----------------

extern "C" void kernel_launch(void* const* d_in, const int* in_sizes, int n_in,
                              void* d_out, int out_size) {
    const float* x  = (const float*)d_in[0];
    const int* ei   = (const int*)d_in[1];    // int32! (JAX x64 disabled)
    const float* W1 = (const float*)d_in[2];
    const float* b1 = (const float*)d_in[3];
    const float* W2 = (const float*)d_in[4];
    const float* b2 = (const float*)d_in[5];
    const float* W3 = (const float*)d_in[6];
    const float* b3 = (const float*)d_in[7];
    float* out      = (float*)d_out;

    const int* src = ei;
    const int* dst = ei + N_EDGES;

    // degree + normalization (shared by all layers)
    deg_init_kernel<<<(N_NODES + 255) / 256, 256>>>();
    deg_count_kernel<<<(N_EDGES + 255) / 256, 256>>>(dst);
    dinv_kernel<<<(N_NODES + 255) / 256, 256>>>();

    const int gemm_blocks = (N_NODES + 63) / 64;
    const int scat_blocks = (N_EDGES * 32) / 256;         // 100000
    const int init128_blocks = (N_NODES * 128 / 4) / 256; // 6250
    const int init64_blocks  = (N_NODES * 64 / 4) / 256;  // 3125

    // Layer 1: h = x @ W1 ; agg = self+bias ; scatter
    gemm_kernel<128, false, false><<<gemm_blocks, 256>>>(x, W1, N_NODES);
    init_agg_kernel<128, false><<<init128_blocks, 256>>>(b1, nullptr);
    scatter_kernel<128, false><<<scat_blocks, 256>>>(src, dst, nullptr);

    // Layer 2: h = relu(agg) @ W2 ; agg = self+bias ; scatter
    gemm_kernel<128, true, true><<<gemm_blocks, 256>>>(nullptr, W2, N_NODES);
    init_agg_kernel<128, false><<<init128_blocks, 256>>>(b2, nullptr);
    scatter_kernel<128, false><<<scat_blocks, 256>>>(src, dst, nullptr);

    // Layer 3: h = relu(agg) @ W3 (N=64) ; out = self+bias ; scatter into d_out
    gemm_kernel<64, true, true><<<gemm_blocks, 256>>>(nullptr, W3, N_NODES);
    init_agg_kernel<64, true><<<init64_blocks, 256>>>(b3, out);
    scatter_kernel<64, true><<<scat_blocks, 256>>>(src, dst, out);
}

// round 4
// speedup vs baseline: 1.9458x; 1.9458x over previous
#include <cuda_runtime.h>

#define N_NODES 50000
#define N_EDGES 800000

// Scratch (__device__ globals; no allocation)
__device__ float g_h[N_NODES * 128];     // GEMM output per layer
__device__ float g_agg[N_NODES * 128];   // aggregation output (layers 1,2)
__device__ int   g_deg[N_NODES];
__device__ float g_dinv[N_NODES];
__device__ int   g_off[N_NODES + 1];     // CSR row offsets (by dst)
__device__ int   g_cursor[N_NODES];      // fill cursors
__device__ int   g_csr_src[N_EDGES];     // src ids grouped by dst

// ---------------- degree / normalization ----------------

__global__ void deg_init_kernel() {
    int i = blockIdx.x * blockDim.x + threadIdx.x;
    if (i < N_NODES) g_deg[i] = 1;  // self loop
}

__global__ void deg_count_kernel(const int* __restrict__ dst) {
    int i = blockIdx.x * blockDim.x + threadIdx.x;
    if (i < N_EDGES) atomicAdd(&g_deg[dst[i]], 1);
}

__global__ void dinv_kernel() {
    int i = blockIdx.x * blockDim.x + threadIdx.x;
    if (i < N_NODES) g_dinv[i] = rsqrtf((float)g_deg[i]);
}

// ---------------- CSR build: exclusive scan of (deg-1), then fill ----------------

__global__ void scan_kernel() {
    __shared__ int buf[1024];
    __shared__ int carry;
    const int tid = threadIdx.x;
    if (tid == 0) carry = 0;
    __syncthreads();
    for (int base = 0; base < N_NODES; base += 1024) {
        int i = base + tid;
        int v = (i < N_NODES) ? (g_deg[i] - 1) : 0;
        buf[tid] = v;
        __syncthreads();
        // inclusive Hillis-Steele scan
        for (int off = 1; off < 1024; off <<= 1) {
            int t = (tid >= off) ? buf[tid - off] : 0;
            __syncthreads();
            buf[tid] += t;
            __syncthreads();
        }
        int excl = buf[tid] - v + carry;
        int total = buf[1023];
        if (i < N_NODES) {
            g_off[i] = excl;
            g_cursor[i] = excl;
        }
        __syncthreads();
        if (tid == 0) carry += total;
        __syncthreads();
    }
    if (tid == 0) g_off[N_NODES] = carry;   // == N_EDGES
}

__global__ void fill_kernel(const int* __restrict__ src, const int* __restrict__ dst) {
    int e = blockIdx.x * blockDim.x + threadIdx.x;
    if (e < N_EDGES) {
        int d = dst[e];
        int pos = atomicAdd(&g_cursor[d], 1);
        g_csr_src[pos] = src[e];
    }
}

// ---------------- dense GEMM: g_h[M,N] = act(X[M,128]) @ W[128,N] ----------------

template<int N, bool RELU, bool FROM_AGG>
__global__ void gemm_kernel(const float* __restrict__ X, const float* __restrict__ W, int M) {
    constexpr int BM = 64, BK = 32, K = 128;
    constexpr int CG = N / 8;
    constexpr int TM = BM * CG / 256;

    __shared__ float Xs[BM][BK + 4];
    __shared__ float Ws[BK][N];

    const float* __restrict__ Xp = FROM_AGG ? (const float*)g_agg : X;
    float* __restrict__ Y = (float*)g_h;

    const int tid = threadIdx.x;
    const int tx = tid % CG;
    const int ty = tid / CG;
    const int m0 = blockIdx.x * BM;

    float acc[TM][8];
#pragma unroll
    for (int r = 0; r < TM; r++)
#pragma unroll
        for (int c = 0; c < 8; c++) acc[r][c] = 0.0f;

#pragma unroll
    for (int kb = 0; kb < K / BK; kb++) {
#pragma unroll
        for (int i = 0; i < 2; i++) {
            int idx = tid + i * 256;
            int row = idx >> 3;
            int kk = (idx & 7) * 4;
            int gm = m0 + row;
            float4 v = make_float4(0.f, 0.f, 0.f, 0.f);
            if (gm < M) v = *(const float4*)&Xp[(size_t)gm * K + kb * BK + kk];
            if (RELU) {
                v.x = fmaxf(v.x, 0.f); v.y = fmaxf(v.y, 0.f);
                v.z = fmaxf(v.z, 0.f); v.w = fmaxf(v.w, 0.f);
            }
            *(float4*)&Xs[row][kk] = v;
        }
        constexpr int WF4 = BK * N / 4;
#pragma unroll
        for (int i = 0; i < WF4 / 256; i++) {
            int idx = tid + i * 256;
            int row = idx / (N / 4);
            int c = (idx % (N / 4)) * 4;
            *(float4*)&Ws[row][c] = *(const float4*)&W[(size_t)(kb * BK + row) * N + c];
        }
        __syncthreads();

#pragma unroll
        for (int k = 0; k < BK; k++) {
            float4 w0 = *(float4*)&Ws[k][tx * 8];
            float4 w1 = *(float4*)&Ws[k][tx * 8 + 4];
#pragma unroll
            for (int r = 0; r < TM; r++) {
                float xv = Xs[ty * TM + r][k];
                acc[r][0] += xv * w0.x; acc[r][1] += xv * w0.y;
                acc[r][2] += xv * w0.z; acc[r][3] += xv * w0.w;
                acc[r][4] += xv * w1.x; acc[r][5] += xv * w1.y;
                acc[r][6] += xv * w1.z; acc[r][7] += xv * w1.w;
            }
        }
        __syncthreads();
    }

#pragma unroll
    for (int r = 0; r < TM; r++) {
        int gm = m0 + ty * TM + r;
        if (gm < M) {
            float4 o0 = make_float4(acc[r][0], acc[r][1], acc[r][2], acc[r][3]);
            float4 o1 = make_float4(acc[r][4], acc[r][5], acc[r][6], acc[r][7]);
            *(float4*)&Y[(size_t)gm * N + tx * 8] = o0;
            *(float4*)&Y[(size_t)gm * N + tx * 8 + 4] = o1;
        }
    }
}

// ---------------- fused gather-aggregate ----------------
// o[d] = g_h[d]*dinv[d]^2 + b + sum_{s in CSR(d)} g_h[s]*dinv[s]*dinv[d]
// One warp per destination node. N=128: float4/lane; N=64: float2/lane.

template<int N, bool TO_OUT>
__global__ void gather_kernel(const float* __restrict__ b, float* __restrict__ out) {
    const int warps_per_block = blockDim.x >> 5;
    const int node = blockIdx.x * warps_per_block + (threadIdx.x >> 5);
    const int lane = threadIdx.x & 31;
    if (node >= N_NODES) return;

    float* __restrict__ o = TO_OUT ? out : (float*)g_agg;
    const float di = g_dinv[node];
    const int beg = g_off[node];
    const int end = g_off[node + 1];

    if (N == 128) {
        const int c = lane * 4;
        float4 acc = *(const float4*)&g_h[(size_t)node * N + c];
        float s2 = di * di;
        acc.x = acc.x * s2 + b[c];
        acc.y = acc.y * s2 + b[c + 1];
        acc.z = acc.z * s2 + b[c + 2];
        acc.w = acc.w * s2 + b[c + 3];

        int e = beg;
        for (; e + 1 < end; e += 2) {
            int s0 = g_csr_src[e];
            int s1 = g_csr_src[e + 1];
            float n0 = g_dinv[s0] * di;
            float n1 = g_dinv[s1] * di;
            float4 v0 = *(const float4*)&g_h[(size_t)s0 * N + c];
            float4 v1 = *(const float4*)&g_h[(size_t)s1 * N + c];
            acc.x += v0.x * n0; acc.y += v0.y * n0;
            acc.z += v0.z * n0; acc.w += v0.w * n0;
            acc.x += v1.x * n1; acc.y += v1.y * n1;
            acc.z += v1.z * n1; acc.w += v1.w * n1;
        }
        if (e < end) {
            int s0 = g_csr_src[e];
            float n0 = g_dinv[s0] * di;
            float4 v0 = *(const float4*)&g_h[(size_t)s0 * N + c];
            acc.x += v0.x * n0; acc.y += v0.y * n0;
            acc.z += v0.z * n0; acc.w += v0.w * n0;
        }
        *(float4*)&o[(size_t)node * N + c] = acc;
    } else {
        const int c = lane * 2;
        float2 acc = *(const float2*)&g_h[(size_t)node * N + c];
        float s2 = di * di;
        acc.x = acc.x * s2 + b[c];
        acc.y = acc.y * s2 + b[c + 1];

        int e = beg;
        for (; e + 1 < end; e += 2) {
            int s0 = g_csr_src[e];
            int s1 = g_csr_src[e + 1];
            float n0 = g_dinv[s0] * di;
            float n1 = g_dinv[s1] * di;
            float2 v0 = *(const float2*)&g_h[(size_t)s0 * N + c];
            float2 v1 = *(const float2*)&g_h[(size_t)s1 * N + c];
            acc.x += v0.x * n0 + v1.x * n1;
            acc.y += v0.y * n0 + v1.y * n1;
        }
        if (e < end) {
            int s0 = g_csr_src[e];
            float n0 = g_dinv[s0] * di;
            float2 v0 = *(const float2*)&g_h[(size_t)s0 * N + c];
            acc.x += v0.x * n0;
            acc.y += v0.y * n0;
        }
        *(float2*)&o[(size_t)node * N + c] = acc;
    }
}

// ---------------- launch ----------------

extern "C" void kernel_launch(void* const* d_in, const int* in_sizes, int n_in,
                              void* d_out, int out_size) {
    const float* x  = (const float*)d_in[0];
    const int* ei   = (const int*)d_in[1];    // int32 (JAX x64 disabled)
    const float* W1 = (const float*)d_in[2];
    const float* b1 = (const float*)d_in[3];
    const float* W2 = (const float*)d_in[4];
    const float* b2 = (const float*)d_in[5];
    const float* W3 = (const float*)d_in[6];
    const float* b3 = (const float*)d_in[7];
    float* out      = (float*)d_out;

    const int* src = ei;
    const int* dst = ei + N_EDGES;

    // degree + normalization + CSR (shared by all layers)
    deg_init_kernel<<<(N_NODES + 255) / 256, 256>>>();
    deg_count_kernel<<<(N_EDGES + 255) / 256, 256>>>(dst);
    dinv_kernel<<<(N_NODES + 255) / 256, 256>>>();
    scan_kernel<<<1, 1024>>>();
    fill_kernel<<<(N_EDGES + 255) / 256, 256>>>(src, dst);

    const int gemm_blocks = (N_NODES + 63) / 64;
    const int gather_blocks = (N_NODES + 7) / 8;   // 8 warps/block

    // Layer 1
    gemm_kernel<128, false, false><<<gemm_blocks, 256>>>(x, W1, N_NODES);
    gather_kernel<128, false><<<gather_blocks, 256>>>(b1, nullptr);

    // Layer 2
    gemm_kernel<128, true, true><<<gemm_blocks, 256>>>(nullptr, W2, N_NODES);
    gather_kernel<128, false><<<gather_blocks, 256>>>(b2, nullptr);

    // Layer 3 (N=64) -> d_out
    gemm_kernel<64, true, true><<<gemm_blocks, 256>>>(nullptr, W3, N_NODES);
    gather_kernel<64, true><<<gather_blocks, 256>>>(b3, out);
}

// round 5
// speedup vs baseline: 2.0242x; 1.0403x over previous
#include <cuda_runtime.h>

#define N_NODES 50000
#define N_EDGES 800000

// Scratch (__device__ globals; no allocation)
__device__ float g_h[N_NODES * 128];     // GEMM output per layer
__device__ float g_agg[N_NODES * 128];   // aggregation output (layers 1,2)
__device__ int   g_deg[N_NODES];
__device__ float g_dinv[N_NODES];
__device__ int   g_off[N_NODES];         // CSR segment start (by dst; unordered alloc)
__device__ int   g_cursor[N_NODES];      // fill cursors
__device__ int   g_csr_src[N_EDGES];     // src ids grouped by dst
__device__ int   g_total;                // bump allocator

// ---------------- degree / normalization ----------------

__global__ void deg_init_kernel() {
    int i = blockIdx.x * blockDim.x + threadIdx.x;
    if (i == 0) g_total = 0;
    if (i < N_NODES) g_deg[i] = 1;  // self loop
}

__global__ void deg_count_kernel(const int* __restrict__ dst) {
    int i = blockIdx.x * blockDim.x + threadIdx.x;
    if (i < N_EDGES) atomicAdd(&g_deg[dst[i]], 1);
}

__global__ void dinv_kernel() {
    int i = blockIdx.x * blockDim.x + threadIdx.x;
    if (i < N_NODES) g_dinv[i] = rsqrtf((float)g_deg[i]);
}

// ---------------- CSR segment allocation (order-free; warp-aggregated atomics) ----------------

__global__ void alloc_kernel() {
    int i = blockIdx.x * blockDim.x + threadIdx.x;
    int lane = threadIdx.x & 31;
    int cnt = (i < N_NODES) ? (g_deg[i] - 1) : 0;
    // warp inclusive scan
    int incl = cnt;
#pragma unroll
    for (int off = 1; off < 32; off <<= 1) {
        int t = __shfl_up_sync(0xffffffffu, incl, off);
        if (lane >= off) incl += t;
    }
    int total = __shfl_sync(0xffffffffu, incl, 31);
    int base = 0;
    if (lane == 0) base = atomicAdd(&g_total, total);
    base = __shfl_sync(0xffffffffu, base, 0);
    if (i < N_NODES) {
        int beg = base + incl - cnt;
        g_off[i] = beg;
        g_cursor[i] = beg;
    }
}

__global__ void fill_kernel(const int* __restrict__ src, const int* __restrict__ dst) {
    int e = blockIdx.x * blockDim.x + threadIdx.x;
    if (e < N_EDGES) {
        int d = dst[e];
        int pos = atomicAdd(&g_cursor[d], 1);
        g_csr_src[pos] = src[e];
    }
}

// ---------------- dense GEMM: g_h[M,N] = act(X[M,128]) @ W[128,N] ----------------
// BM=128, 256 threads, microtile 8 x TN (TN = N/16). Xs stored k-major (transposed).

template<int N, bool RELU, bool FROM_AGG>
__global__ void __launch_bounds__(256) gemm_kernel(const float* __restrict__ X,
                                                   const float* __restrict__ W, int M) {
    constexpr int BM = 128, BK = 32, K = 128;
    constexpr int PAD = 4;
    constexpr int TN = N / 16;           // 8 (N=128) or 4 (N=64)

    __shared__ float Xs[BK][BM + PAD];
    __shared__ float Ws[BK][N];

    const float* __restrict__ Xp = FROM_AGG ? (const float*)g_agg : X;
    float* __restrict__ Y = (float*)g_h;

    const int tid = threadIdx.x;
    const int tx = tid % 16;             // col group: cols [tx*TN, tx*TN+TN)
    const int ty = tid / 16;             // row group: rows [ty*8, ty*8+8)
    const int m0 = blockIdx.x * BM;

    float acc[8][TN];
#pragma unroll
    for (int r = 0; r < 8; r++)
#pragma unroll
        for (int c = 0; c < TN; c++) acc[r][c] = 0.0f;

#pragma unroll
    for (int kb = 0; kb < K / BK; kb++) {
        // X tile: BM x BK = 1024 float4, 4 per thread; store transposed into Xs[k][row]
#pragma unroll
        for (int i = 0; i < 4; i++) {
            int idx = tid + i * 256;
            int row = idx >> 3;                 // 0..127
            int kk = (idx & 7) * 4;             // 0..28
            int gm = m0 + row;
            float4 v = make_float4(0.f, 0.f, 0.f, 0.f);
            if (gm < M) v = *(const float4*)&Xp[(size_t)gm * K + kb * BK + kk];
            if (RELU) {
                v.x = fmaxf(v.x, 0.f); v.y = fmaxf(v.y, 0.f);
                v.z = fmaxf(v.z, 0.f); v.w = fmaxf(v.w, 0.f);
            }
            Xs[kk + 0][row] = v.x;
            Xs[kk + 1][row] = v.y;
            Xs[kk + 2][row] = v.z;
            Xs[kk + 3][row] = v.w;
        }
        // W tile: BK x N floats
        constexpr int WF4 = BK * N / 4;         // 1024 or 512
#pragma unroll
        for (int i = 0; i < WF4 / 256; i++) {
            int idx = tid + i * 256;
            int row = idx / (N / 4);
            int c = (idx % (N / 4)) * 4;
            *(float4*)&Ws[row][c] = *(const float4*)&W[(size_t)(kb * BK + row) * N + c];
        }
        __syncthreads();

#pragma unroll
        for (int k = 0; k < BK; k++) {
            float xv[8];
            *(float4*)&xv[0] = *(float4*)&Xs[k][ty * 8];
            *(float4*)&xv[4] = *(float4*)&Xs[k][ty * 8 + 4];
            float wv[TN];
#pragma unroll
            for (int j = 0; j < TN / 4; j++)
                *(float4*)&wv[j * 4] = *(float4*)&Ws[k][tx * TN + j * 4];
#pragma unroll
            for (int r = 0; r < 8; r++)
#pragma unroll
                for (int c = 0; c < TN; c++)
                    acc[r][c] += xv[r] * wv[c];
        }
        __syncthreads();
    }

#pragma unroll
    for (int r = 0; r < 8; r++) {
        int gm = m0 + ty * 8 + r;
        if (gm < M) {
#pragma unroll
            for (int j = 0; j < TN / 4; j++) {
                float4 o = make_float4(acc[r][j * 4], acc[r][j * 4 + 1],
                                       acc[r][j * 4 + 2], acc[r][j * 4 + 3]);
                *(float4*)&Y[(size_t)gm * N + tx * TN + j * 4] = o;
            }
        }
    }
}

// ---------------- fused gather-aggregate ----------------
// o[d] = g_h[d]*dinv[d]^2 + b + sum_{s in CSR(d)} g_h[s]*dinv[s]*dinv[d]

template<int N, bool TO_OUT>
__global__ void gather_kernel(const float* __restrict__ b, float* __restrict__ out) {
    const int warps_per_block = blockDim.x >> 5;
    const int node = blockIdx.x * warps_per_block + (threadIdx.x >> 5);
    const int lane = threadIdx.x & 31;
    if (node >= N_NODES) return;

    float* __restrict__ o = TO_OUT ? out : (float*)g_agg;
    const float di = g_dinv[node];
    const int beg = g_off[node];
    const int end = beg + g_deg[node] - 1;

    if (N == 128) {
        const int c = lane * 4;
        float4 acc = *(const float4*)&g_h[(size_t)node * N + c];
        float s2 = di * di;
        acc.x = acc.x * s2 + b[c];
        acc.y = acc.y * s2 + b[c + 1];
        acc.z = acc.z * s2 + b[c + 2];
        acc.w = acc.w * s2 + b[c + 3];

        int e = beg;
        for (; e + 1 < end; e += 2) {
            int s0 = g_csr_src[e];
            int s1 = g_csr_src[e + 1];
            float n0 = g_dinv[s0] * di;
            float n1 = g_dinv[s1] * di;
            float4 v0 = *(const float4*)&g_h[(size_t)s0 * N + c];
            float4 v1 = *(const float4*)&g_h[(size_t)s1 * N + c];
            acc.x += v0.x * n0; acc.y += v0.y * n0;
            acc.z += v0.z * n0; acc.w += v0.w * n0;
            acc.x += v1.x * n1; acc.y += v1.y * n1;
            acc.z += v1.z * n1; acc.w += v1.w * n1;
        }
        if (e < end) {
            int s0 = g_csr_src[e];
            float n0 = g_dinv[s0] * di;
            float4 v0 = *(const float4*)&g_h[(size_t)s0 * N + c];
            acc.x += v0.x * n0; acc.y += v0.y * n0;
            acc.z += v0.z * n0; acc.w += v0.w * n0;
        }
        *(float4*)&o[(size_t)node * N + c] = acc;
    } else {
        const int c = lane * 2;
        float2 acc = *(const float2*)&g_h[(size_t)node * N + c];
        float s2 = di * di;
        acc.x = acc.x * s2 + b[c];
        acc.y = acc.y * s2 + b[c + 1];

        int e = beg;
        for (; e + 1 < end; e += 2) {
            int s0 = g_csr_src[e];
            int s1 = g_csr_src[e + 1];
            float n0 = g_dinv[s0] * di;
            float n1 = g_dinv[s1] * di;
            float2 v0 = *(const float2*)&g_h[(size_t)s0 * N + c];
            float2 v1 = *(const float2*)&g_h[(size_t)s1 * N + c];
            acc.x += v0.x * n0 + v1.x * n1;
            acc.y += v0.y * n0 + v1.y * n1;
        }
        if (e < end) {
            int s0 = g_csr_src[e];
            float n0 = g_dinv[s0] * di;
            float2 v0 = *(const float2*)&g_h[(size_t)s0 * N + c];
            acc.x += v0.x * n0;
            acc.y += v0.y * n0;
        }
        *(float2*)&o[(size_t)node * N + c] = acc;
    }
}

// ---------------- launch ----------------

extern "C" void kernel_launch(void* const* d_in, const int* in_sizes, int n_in,
                              void* d_out, int out_size) {
    const float* x  = (const float*)d_in[0];
    const int* ei   = (const int*)d_in[1];    // int32 (JAX x64 disabled)
    const float* W1 = (const float*)d_in[2];
    const float* b1 = (const float*)d_in[3];
    const float* W2 = (const float*)d_in[4];
    const float* b2 = (const float*)d_in[5];
    const float* W3 = (const float*)d_in[6];
    const float* b3 = (const float*)d_in[7];
    float* out      = (float*)d_out;

    const int* src = ei;
    const int* dst = ei + N_EDGES;

    // degree + normalization + CSR (shared by all layers)
    deg_init_kernel<<<(N_NODES + 255) / 256, 256>>>();
    deg_count_kernel<<<(N_EDGES + 255) / 256, 256>>>(dst);
    dinv_kernel<<<(N_NODES + 255) / 256, 256>>>();
    alloc_kernel<<<(N_NODES + 255) / 256, 256>>>();
    fill_kernel<<<(N_EDGES + 255) / 256, 256>>>(src, dst);

    const int gemm_blocks = (N_NODES + 127) / 128;
    const int gather_blocks = (N_NODES + 7) / 8;   // 8 warps/block

    // Layer 1
    gemm_kernel<128, false, false><<<gemm_blocks, 256>>>(x, W1, N_NODES);
    gather_kernel<128, false><<<gather_blocks, 256>>>(b1, nullptr);

    // Layer 2
    gemm_kernel<128, true, true><<<gemm_blocks, 256>>>(nullptr, W2, N_NODES);
    gather_kernel<128, false><<<gather_blocks, 256>>>(b2, nullptr);

    // Layer 3 (N=64) -> d_out
    gemm_kernel<64, true, true><<<gemm_blocks, 256>>>(nullptr, W3, N_NODES);
    gather_kernel<64, true><<<gather_blocks, 256>>>(b3, out);
}

// round 6
// speedup vs baseline: 2.0995x; 1.0372x over previous
#include <cuda_runtime.h>

#define N_NODES 50000
#define N_EDGES 800000

// Scratch (__device__ globals; no allocation)
__device__ float g_h[N_NODES * 128];     // GEMM output per layer, pre-scaled by dinv[row]
__device__ float g_agg[N_NODES * 128];   // aggregation output (layers 1,2)
__device__ int   g_deg[N_NODES];
__device__ float g_dinv[N_NODES];
__device__ int   g_off[N_NODES];         // CSR segment start (by dst; unordered alloc)
__device__ int   g_cursor[N_NODES];      // fill cursors
__device__ int   g_csr_src[N_EDGES];     // src ids grouped by dst
__device__ int   g_total;                // bump allocator

// ---------------- degree / normalization ----------------

__global__ void deg_init_kernel() {
    int i = blockIdx.x * blockDim.x + threadIdx.x;
    if (i == 0) g_total = 0;
    if (i < N_NODES) g_deg[i] = 1;  // self loop
}

__global__ void deg_count_kernel(const int* __restrict__ dst) {
    int i = blockIdx.x * blockDim.x + threadIdx.x;
    if (i < N_EDGES) atomicAdd(&g_deg[dst[i]], 1);
}

__global__ void dinv_kernel() {
    int i = blockIdx.x * blockDim.x + threadIdx.x;
    if (i < N_NODES) g_dinv[i] = rsqrtf((float)g_deg[i]);
}

// ---------------- CSR segment allocation (order-free; warp-aggregated atomics) ----------------

__global__ void alloc_kernel() {
    int i = blockIdx.x * blockDim.x + threadIdx.x;
    int lane = threadIdx.x & 31;
    int cnt = (i < N_NODES) ? (g_deg[i] - 1) : 0;
    int incl = cnt;
#pragma unroll
    for (int off = 1; off < 32; off <<= 1) {
        int t = __shfl_up_sync(0xffffffffu, incl, off);
        if (lane >= off) incl += t;
    }
    int total = __shfl_sync(0xffffffffu, incl, 31);
    int base = 0;
    if (lane == 0) base = atomicAdd(&g_total, total);
    base = __shfl_sync(0xffffffffu, base, 0);
    if (i < N_NODES) {
        int beg = base + incl - cnt;
        g_off[i] = beg;
        g_cursor[i] = beg;
    }
}

__global__ void fill_kernel(const int* __restrict__ src, const int* __restrict__ dst) {
    int e = blockIdx.x * blockDim.x + threadIdx.x;
    if (e < N_EDGES) {
        int d = dst[e];
        int pos = atomicAdd(&g_cursor[d], 1);
        g_csr_src[pos] = src[e];
    }
}

// ---------------- dense GEMM: g_h[M,N] = act(X[M,128]) @ W[128,N] * dinv[row] ----------------
// BM=128, 256 threads, microtile 8 x TN. Epilogue scales each row by dinv[row].

template<int N, bool RELU, bool FROM_AGG>
__global__ void __launch_bounds__(256) gemm_kernel(const float* __restrict__ X,
                                                   const float* __restrict__ W, int M) {
    constexpr int BM = 128, BK = 32, K = 128;
    constexpr int PAD = 4;
    constexpr int TN = N / 16;           // 8 (N=128) or 4 (N=64)

    __shared__ float Xs[BK][BM + PAD];
    __shared__ float Ws[BK][N];

    const float* __restrict__ Xp = FROM_AGG ? (const float*)g_agg : X;
    float* __restrict__ Y = (float*)g_h;

    const int tid = threadIdx.x;
    const int tx = tid % 16;
    const int ty = tid / 16;
    const int m0 = blockIdx.x * BM;

    float acc[8][TN];
#pragma unroll
    for (int r = 0; r < 8; r++)
#pragma unroll
        for (int c = 0; c < TN; c++) acc[r][c] = 0.0f;

#pragma unroll
    for (int kb = 0; kb < K / BK; kb++) {
#pragma unroll
        for (int i = 0; i < 4; i++) {
            int idx = tid + i * 256;
            int row = idx >> 3;
            int kk = (idx & 7) * 4;
            int gm = m0 + row;
            float4 v = make_float4(0.f, 0.f, 0.f, 0.f);
            if (gm < M) v = *(const float4*)&Xp[(size_t)gm * K + kb * BK + kk];
            if (RELU) {
                v.x = fmaxf(v.x, 0.f); v.y = fmaxf(v.y, 0.f);
                v.z = fmaxf(v.z, 0.f); v.w = fmaxf(v.w, 0.f);
            }
            Xs[kk + 0][row] = v.x;
            Xs[kk + 1][row] = v.y;
            Xs[kk + 2][row] = v.z;
            Xs[kk + 3][row] = v.w;
        }
        constexpr int WF4 = BK * N / 4;
#pragma unroll
        for (int i = 0; i < WF4 / 256; i++) {
            int idx = tid + i * 256;
            int row = idx / (N / 4);
            int c = (idx % (N / 4)) * 4;
            *(float4*)&Ws[row][c] = *(const float4*)&W[(size_t)(kb * BK + row) * N + c];
        }
        __syncthreads();

#pragma unroll
        for (int k = 0; k < BK; k++) {
            float xv[8];
            *(float4*)&xv[0] = *(float4*)&Xs[k][ty * 8];
            *(float4*)&xv[4] = *(float4*)&Xs[k][ty * 8 + 4];
            float wv[TN];
#pragma unroll
            for (int j = 0; j < TN / 4; j++)
                *(float4*)&wv[j * 4] = *(float4*)&Ws[k][tx * TN + j * 4];
#pragma unroll
            for (int r = 0; r < 8; r++)
#pragma unroll
                for (int c = 0; c < TN; c++)
                    acc[r][c] += xv[r] * wv[c];
        }
        __syncthreads();
    }

#pragma unroll
    for (int r = 0; r < 8; r++) {
        int gm = m0 + ty * 8 + r;
        if (gm < M) {
            float s = g_dinv[gm];
#pragma unroll
            for (int j = 0; j < TN / 4; j++) {
                float4 o = make_float4(acc[r][j * 4] * s, acc[r][j * 4 + 1] * s,
                                       acc[r][j * 4 + 2] * s, acc[r][j * 4 + 3] * s);
                *(float4*)&Y[(size_t)gm * N + tx * TN + j * 4] = o;
            }
        }
    }
}

// ---------------- fused gather-aggregate ----------------
// g_h rows are pre-scaled by dinv[src].
// o[d] = ( g_h[d] + sum_{s in CSR(d)} g_h[s] ) * dinv[d] + b

template<int N, bool TO_OUT>
__global__ void gather_kernel(const float* __restrict__ b, float* __restrict__ out) {
    const int warps_per_block = blockDim.x >> 5;
    const int node = blockIdx.x * warps_per_block + (threadIdx.x >> 5);
    const int lane = threadIdx.x & 31;
    if (node >= N_NODES) return;

    float* __restrict__ o = TO_OUT ? out : (float*)g_agg;
    const float di = g_dinv[node];
    const int beg = g_off[node];
    const int end = beg + g_deg[node] - 1;

    if (N == 128) {
        const int c = lane * 4;
        float4 acc = *(const float4*)&g_h[(size_t)node * N + c];

        int e = beg;
        for (; e + 4 <= end; e += 4) {
            int s0 = g_csr_src[e];
            int s1 = g_csr_src[e + 1];
            int s2 = g_csr_src[e + 2];
            int s3 = g_csr_src[e + 3];
            float4 v0 = *(const float4*)&g_h[(size_t)s0 * N + c];
            float4 v1 = *(const float4*)&g_h[(size_t)s1 * N + c];
            float4 v2 = *(const float4*)&g_h[(size_t)s2 * N + c];
            float4 v3 = *(const float4*)&g_h[(size_t)s3 * N + c];
            acc.x += v0.x + v1.x + v2.x + v3.x;
            acc.y += v0.y + v1.y + v2.y + v3.y;
            acc.z += v0.z + v1.z + v2.z + v3.z;
            acc.w += v0.w + v1.w + v2.w + v3.w;
        }
        for (; e < end; e++) {
            int s0 = g_csr_src[e];
            float4 v0 = *(const float4*)&g_h[(size_t)s0 * N + c];
            acc.x += v0.x; acc.y += v0.y; acc.z += v0.z; acc.w += v0.w;
        }
        acc.x = acc.x * di + b[c];
        acc.y = acc.y * di + b[c + 1];
        acc.z = acc.z * di + b[c + 2];
        acc.w = acc.w * di + b[c + 3];
        *(float4*)&o[(size_t)node * N + c] = acc;
    } else {
        const int c = lane * 2;
        float2 acc = *(const float2*)&g_h[(size_t)node * N + c];

        int e = beg;
        for (; e + 4 <= end; e += 4) {
            int s0 = g_csr_src[e];
            int s1 = g_csr_src[e + 1];
            int s2 = g_csr_src[e + 2];
            int s3 = g_csr_src[e + 3];
            float2 v0 = *(const float2*)&g_h[(size_t)s0 * N + c];
            float2 v1 = *(const float2*)&g_h[(size_t)s1 * N + c];
            float2 v2 = *(const float2*)&g_h[(size_t)s2 * N + c];
            float2 v3 = *(const float2*)&g_h[(size_t)s3 * N + c];
            acc.x += v0.x + v1.x + v2.x + v3.x;
            acc.y += v0.y + v1.y + v2.y + v3.y;
        }
        for (; e < end; e++) {
            int s0 = g_csr_src[e];
            float2 v0 = *(const float2*)&g_h[(size_t)s0 * N + c];
            acc.x += v0.x; acc.y += v0.y;
        }
        acc.x = acc.x * di + b[c];
        acc.y = acc.y * di + b[c + 1];
        *(float2*)&o[(size_t)node * N + c] = acc;
    }
}

// ---------------- launch ----------------

extern "C" void kernel_launch(void* const* d_in, const int* in_sizes, int n_in,
                              void* d_out, int out_size) {
    const float* x  = (const float*)d_in[0];
    const int* ei   = (const int*)d_in[1];    // int32 (JAX x64 disabled)
    const float* W1 = (const float*)d_in[2];
    const float* b1 = (const float*)d_in[3];
    const float* W2 = (const float*)d_in[4];
    const float* b2 = (const float*)d_in[5];
    const float* W3 = (const float*)d_in[6];
    const float* b3 = (const float*)d_in[7];
    float* out      = (float*)d_out;

    const int* src = ei;
    const int* dst = ei + N_EDGES;

    // degree + normalization + CSR (shared by all layers)
    deg_init_kernel<<<(N_NODES + 255) / 256, 256>>>();
    deg_count_kernel<<<(N_EDGES + 255) / 256, 256>>>(dst);
    dinv_kernel<<<(N_NODES + 255) / 256, 256>>>();
    alloc_kernel<<<(N_NODES + 255) / 256, 256>>>();
    fill_kernel<<<(N_EDGES + 255) / 256, 256>>>(src, dst);

    const int gemm_blocks = (N_NODES + 127) / 128;
    const int gather_blocks = (N_NODES + 7) / 8;   // 8 warps/block

    // Layer 1
    gemm_kernel<128, false, false><<<gemm_blocks, 256>>>(x, W1, N_NODES);
    gather_kernel<128, false><<<gather_blocks, 256>>>(b1, nullptr);

    // Layer 2
    gemm_kernel<128, true, true><<<gemm_blocks, 256>>>(nullptr, W2, N_NODES);
    gather_kernel<128, false><<<gather_blocks, 256>>>(b2, nullptr);

    // Layer 3 (N=64) -> d_out
    gemm_kernel<64, true, true><<<gemm_blocks, 256>>>(nullptr, W3, N_NODES);
    gather_kernel<64, true><<<gather_blocks, 256>>>(b3, out);
}

// round 8
// speedup vs baseline: 4.2312x; 2.0154x over previous
#include <cuda_runtime.h>
#include <cuda_bf16.h>
#include <cstdint>

#define N_NODES 50000
#define N_EDGES 800000

// Scratch (__device__ globals; no allocation)
__device__ float g_h[N_NODES * 128];     // GEMM output per layer, pre-scaled by dinv[row]
__device__ float g_agg[N_NODES * 128];   // aggregation output (layers 1,2)
__device__ int   g_deg[N_NODES];
__device__ float g_dinv[N_NODES];
__device__ int   g_off[N_NODES];         // CSR segment start (by dst; unordered alloc)
__device__ int   g_cursor[N_NODES];      // fill cursors
__device__ int   g_csr_src[N_EDGES];     // src ids grouped by dst
__device__ int   g_total;                // bump allocator

// ---------------- degree / normalization ----------------

__global__ void deg_init_kernel() {
    int i = blockIdx.x * blockDim.x + threadIdx.x;
    if (i == 0) g_total = 0;
    if (i < N_NODES) g_deg[i] = 1;  // self loop
}

__global__ void deg_count_kernel(const int* __restrict__ dst) {
    int i = blockIdx.x * blockDim.x + threadIdx.x;
    if (i < N_EDGES) atomicAdd(&g_deg[dst[i]], 1);
}

__global__ void dinv_kernel() {
    int i = blockIdx.x * blockDim.x + threadIdx.x;
    if (i < N_NODES) g_dinv[i] = rsqrtf((float)g_deg[i]);
}

// ---------------- CSR segment allocation ----------------

__global__ void alloc_kernel() {
    int i = blockIdx.x * blockDim.x + threadIdx.x;
    int lane = threadIdx.x & 31;
    int cnt = (i < N_NODES) ? (g_deg[i] - 1) : 0;
    int incl = cnt;
#pragma unroll
    for (int off = 1; off < 32; off <<= 1) {
        int t = __shfl_up_sync(0xffffffffu, incl, off);
        if (lane >= off) incl += t;
    }
    int total = __shfl_sync(0xffffffffu, incl, 31);
    int base = 0;
    if (lane == 0) base = atomicAdd(&g_total, total);
    base = __shfl_sync(0xffffffffu, base, 0);
    if (i < N_NODES) {
        int beg = base + incl - cnt;
        g_off[i] = beg;
        g_cursor[i] = beg;
    }
}

__global__ void fill_kernel(const int* __restrict__ src, const int* __restrict__ dst) {
    int e = blockIdx.x * blockDim.x + threadIdx.x;
    if (e < N_EDGES) {
        int d = dst[e];
        int pos = atomicAdd(&g_cursor[d], 1);
        g_csr_src[pos] = src[e];
    }
}

// ================= bf16x3 mma.sync GEMM =================
// g_h[M,N] = ( act(X[M,128]) @ W[128,N] ) * dinv[row]
// fp32 -> bf16 hi+lo; D = Xhi*Whi + Xhi*Wlo + Xlo*Whi (fp32 accum in HMMA).

__device__ __forceinline__ uint32_t smem_u32(const void* p) {
    return (uint32_t)__cvta_generic_to_shared(p);
}

__device__ __forceinline__ void ldsm4(uint32_t* r, uint32_t addr) {
    asm volatile("ldmatrix.sync.aligned.m8n8.x4.shared.b16 {%0,%1,%2,%3}, [%4];"
                 : "=r"(r[0]), "=r"(r[1]), "=r"(r[2]), "=r"(r[3]) : "r"(addr));
}

__device__ __forceinline__ void mma16816(float* d, const uint32_t* a,
                                         uint32_t b0, uint32_t b1) {
    asm volatile(
        "mma.sync.aligned.m16n8k16.row.col.f32.bf16.bf16.f32 "
        "{%0,%1,%2,%3}, {%4,%5,%6,%7}, {%8,%9}, {%0,%1,%2,%3};"
        : "+f"(d[0]), "+f"(d[1]), "+f"(d[2]), "+f"(d[3])
        : "r"(a[0]), "r"(a[1]), "r"(a[2]), "r"(a[3]), "r"(b0), "r"(b1));
}

__device__ __forceinline__ void split8(const float* v, uint4& hi, uint4& lo) {
    uint32_t h[4], l[4];
#pragma unroll
    for (int j = 0; j < 4; j++) {
        __nv_bfloat16 h0 = __float2bfloat16(v[2 * j]);
        __nv_bfloat16 h1 = __float2bfloat16(v[2 * j + 1]);
        float f0 = __bfloat162float(h0), f1 = __bfloat162float(h1);
        __nv_bfloat162 hh = __halves2bfloat162(h0, h1);
        __nv_bfloat162 ll = __halves2bfloat162(__float2bfloat16(v[2 * j] - f0),
                                               __float2bfloat16(v[2 * j + 1] - f1));
        h[j] = *reinterpret_cast<uint32_t*>(&hh);
        l[j] = *reinterpret_cast<uint32_t*>(&ll);
    }
    hi = make_uint4(h[0], h[1], h[2], h[3]);
    lo = make_uint4(l[0], l[1], l[2], l[3]);
}

// Block: 128(M) x N, K=128 resident. 8 warps in 4x2; warp tile 32 x N/2.
template<int N, bool RELU, bool FROM_AGG>
__global__ void __launch_bounds__(256) gemm_mma_kernel(const float* __restrict__ X,
                                                       const float* __restrict__ W, int M) {
    constexpr int K = 128, BM = 128, SB = 136;   // row pad: 272B stride, conflict-free LDSM
    constexpr int A_ELE = BM * SB;
    constexpr int B_ELE = N * SB;
    constexpr int NA = N / 16;                   // n-atoms (m16n8) per warp

    extern __shared__ __nv_bfloat16 sm[];
    __nv_bfloat16* Ahi = sm;
    __nv_bfloat16* Alo = sm + A_ELE;
    __nv_bfloat16* Bhi = sm + 2 * A_ELE;
    __nv_bfloat16* Blo = sm + 2 * A_ELE + B_ELE;

    const float* __restrict__ Xp = FROM_AGG ? (const float*)g_agg : X;
    const int tid = threadIdx.x;
    const int m0 = blockIdx.x * BM;

    // ---- load + split X: thread = (row, half-row of 64) ----
    {
        const int row = tid >> 1;
        const int kh = (tid & 1) * 64;
        const int gm = m0 + row;
        float v[8];
#pragma unroll
        for (int c0 = 0; c0 < 64; c0 += 8) {
            if (gm < M) {
                float4 a = *(const float4*)&Xp[(size_t)gm * K + kh + c0];
                float4 b = *(const float4*)&Xp[(size_t)gm * K + kh + c0 + 4];
                v[0] = a.x; v[1] = a.y; v[2] = a.z; v[3] = a.w;
                v[4] = b.x; v[5] = b.y; v[6] = b.z; v[7] = b.w;
                if (RELU) {
#pragma unroll
                    for (int j = 0; j < 8; j++) v[j] = fmaxf(v[j], 0.f);
                }
            } else {
#pragma unroll
                for (int j = 0; j < 8; j++) v[j] = 0.f;
            }
            uint4 hi, lo;
            split8(v, hi, lo);
            *(uint4*)&Ahi[row * SB + kh + c0] = hi;
            *(uint4*)&Alo[row * SB + kh + c0] = lo;
        }
    }

    // ---- load + split W transposed: Bsm[n][k] = W[k][n] ----
    {
        constexpr int TPR = 256 / N;             // threads per output col (2 or 4)
        constexpr int KS = K / TPR;              // k-span per thread (64 or 32)
        const int n = tid % N;
        const int kh = (tid / N) * KS;
        float v[8];
#pragma unroll
        for (int c0 = 0; c0 < KS; c0 += 8) {
#pragma unroll
            for (int j = 0; j < 8; j++) v[j] = W[(size_t)(kh + c0 + j) * N + n];
            uint4 hi, lo;
            split8(v, hi, lo);
            *(uint4*)&Bhi[n * SB + kh + c0] = hi;
            *(uint4*)&Blo[n * SB + kh + c0] = lo;
        }
    }
    __syncthreads();

    const uint32_t aHi = smem_u32(Ahi), aLo = smem_u32(Alo);
    const uint32_t bHi = smem_u32(Bhi), bLo = smem_u32(Blo);
    const int wid = tid >> 5, lane = tid & 31;
    const int mb = (wid & 3) * 32;               // warp row base
    const int nb = (wid >> 2) * (N / 2);         // warp col base

    float acc[2][NA][4];
#pragma unroll
    for (int mi = 0; mi < 2; mi++)
#pragma unroll
        for (int ni = 0; ni < NA; ni++)
#pragma unroll
            for (int j = 0; j < 4; j++) acc[mi][ni][j] = 0.f;

    const int l3 = lane >> 3;
    // A lane addr: rows mb + (lane&15), k half by lane>>4
    const uint32_t offA = (uint32_t)((mb + (lane & 15)) * SB + ((lane >> 4) << 3)) * 2;
    // B lane addr: tiles (n0-7,k0-7),(n0-7,k8-15),(n8-15,k0-7),(n8-15,k8-15)
    const uint32_t offB = (uint32_t)((nb + ((l3 >> 1) << 3) + (lane & 7)) * SB + ((l3 & 1) << 3)) * 2;

#pragma unroll
    for (int ks = 0; ks < 8; ks++) {
        const uint32_t kofs = (uint32_t)(ks * 16 * 2);
        uint32_t ah[2][4], al[2][4];
        ldsm4(ah[0], aHi + offA + kofs);
        ldsm4(ah[1], aHi + offA + kofs + 16 * SB * 2);
        ldsm4(al[0], aLo + offA + kofs);
        ldsm4(al[1], aLo + offA + kofs + 16 * SB * 2);

        uint32_t bh[NA][2], bl[NA][2];
#pragma unroll
        for (int nq = 0; nq < NA / 2; nq++) {
            uint32_t r[4];
            ldsm4(r, bHi + offB + kofs + nq * 16 * SB * 2);
            bh[2 * nq][0] = r[0]; bh[2 * nq][1] = r[1];
            bh[2 * nq + 1][0] = r[2]; bh[2 * nq + 1][1] = r[3];
            ldsm4(r, bLo + offB + kofs + nq * 16 * SB * 2);
            bl[2 * nq][0] = r[0]; bl[2 * nq][1] = r[1];
            bl[2 * nq + 1][0] = r[2]; bl[2 * nq + 1][1] = r[3];
        }

#pragma unroll
        for (int mi = 0; mi < 2; mi++)
#pragma unroll
            for (int ni = 0; ni < NA; ni++) {
                mma16816(acc[mi][ni], ah[mi], bh[ni][0], bh[ni][1]);
                mma16816(acc[mi][ni], ah[mi], bl[ni][0], bl[ni][1]);
                mma16816(acc[mi][ni], al[mi], bh[ni][0], bh[ni][1]);
            }
    }

    // ---- epilogue: scale by dinv[row], store ----
    const int g = lane >> 2, tg = lane & 3;
#pragma unroll
    for (int mi = 0; mi < 2; mi++) {
        const int r0 = m0 + mb + mi * 16 + g;
        const int r1 = r0 + 8;
        const float s0 = (r0 < M) ? g_dinv[r0] : 0.f;
        const float s1 = (r1 < M) ? g_dinv[r1] : 0.f;
#pragma unroll
        for (int ni = 0; ni < NA; ni++) {
            const int col = nb + ni * 8 + tg * 2;
            if (r0 < M) {
                float2 o = make_float2(acc[mi][ni][0] * s0, acc[mi][ni][1] * s0);
                *(float2*)&g_h[(size_t)r0 * N + col] = o;
            }
            if (r1 < M) {
                float2 o = make_float2(acc[mi][ni][2] * s1, acc[mi][ni][3] * s1);
                *(float2*)&g_h[(size_t)r1 * N + col] = o;
            }
        }
    }
}

// ---------------- fused gather-aggregate ----------------
// g_h rows pre-scaled by dinv[src]. o[d] = (g_h[d] + sum g_h[s]) * dinv[d] + b

template<int N, bool TO_OUT>
__global__ void gather_kernel(const float* __restrict__ b, float* __restrict__ out) {
    const int warps_per_block = blockDim.x >> 5;
    const int node = blockIdx.x * warps_per_block + (threadIdx.x >> 5);
    const int lane = threadIdx.x & 31;
    if (node >= N_NODES) return;

    float* __restrict__ o = TO_OUT ? out : (float*)g_agg;
    const float di = g_dinv[node];
    const int beg = g_off[node];
    const int end = beg + g_deg[node] - 1;

    if (N == 128) {
        const int c = lane * 4;
        float4 acc = *(const float4*)&g_h[(size_t)node * N + c];
        int e = beg;
        for (; e + 4 <= end; e += 4) {
            int s0 = g_csr_src[e];
            int s1 = g_csr_src[e + 1];
            int s2 = g_csr_src[e + 2];
            int s3 = g_csr_src[e + 3];
            float4 v0 = *(const float4*)&g_h[(size_t)s0 * N + c];
            float4 v1 = *(const float4*)&g_h[(size_t)s1 * N + c];
            float4 v2 = *(const float4*)&g_h[(size_t)s2 * N + c];
            float4 v3 = *(const float4*)&g_h[(size_t)s3 * N + c];
            acc.x += v0.x + v1.x + v2.x + v3.x;
            acc.y += v0.y + v1.y + v2.y + v3.y;
            acc.z += v0.z + v1.z + v2.z + v3.z;
            acc.w += v0.w + v1.w + v2.w + v3.w;
        }
        for (; e < end; e++) {
            int s0 = g_csr_src[e];
            float4 v0 = *(const float4*)&g_h[(size_t)s0 * N + c];
            acc.x += v0.x; acc.y += v0.y; acc.z += v0.z; acc.w += v0.w;
        }
        acc.x = acc.x * di + b[c];
        acc.y = acc.y * di + b[c + 1];
        acc.z = acc.z * di + b[c + 2];
        acc.w = acc.w * di + b[c + 3];
        *(float4*)&o[(size_t)node * N + c] = acc;
    } else {
        const int c = lane * 2;
        float2 acc = *(const float2*)&g_h[(size_t)node * N + c];
        int e = beg;
        for (; e + 4 <= end; e += 4) {
            int s0 = g_csr_src[e];
            int s1 = g_csr_src[e + 1];
            int s2 = g_csr_src[e + 2];
            int s3 = g_csr_src[e + 3];
            float2 v0 = *(const float2*)&g_h[(size_t)s0 * N + c];
            float2 v1 = *(const float2*)&g_h[(size_t)s1 * N + c];
            float2 v2 = *(const float2*)&g_h[(size_t)s2 * N + c];
            float2 v3 = *(const float2*)&g_h[(size_t)s3 * N + c];
            acc.x += v0.x + v1.x + v2.x + v3.x;
            acc.y += v0.y + v1.y + v2.y + v3.y;
        }
        for (; e < end; e++) {
            int s0 = g_csr_src[e];
            float2 v0 = *(const float2*)&g_h[(size_t)s0 * N + c];
            acc.x += v0.x; acc.y += v0.y;
        }
        acc.x = acc.x * di + b[c];
        acc.y = acc.y * di + b[c + 1];
        *(float2*)&o[(size_t)node * N + c] = acc;
    }
}

// ---------------- launch ----------------

extern "C" void kernel_launch(void* const* d_in, const int* in_sizes, int n_in,
                              void* d_out, int out_size) {
    const float* x  = (const float*)d_in[0];
    const int* ei   = (const int*)d_in[1];    // int32 (JAX x64 disabled)
    const float* W1 = (const float*)d_in[2];
    const float* b1 = (const float*)d_in[3];
    const float* W2 = (const float*)d_in[4];
    const float* b2 = (const float*)d_in[5];
    const float* W3 = (const float*)d_in[6];
    const float* b3 = (const float*)d_in[7];
    float* out      = (float*)d_out;

    const int* src = ei;
    const int* dst = ei + N_EDGES;

    constexpr int SB = 136;
    constexpr int SMEM_128 = (2 * 128 * SB + 2 * 128 * SB) * 2;  // 139264
    constexpr int SMEM_64  = (2 * 128 * SB + 2 * 64 * SB) * 2;   // 104448
    cudaFuncSetAttribute(gemm_mma_kernel<128, false, false>,
                         cudaFuncAttributeMaxDynamicSharedMemorySize, SMEM_128);
    cudaFuncSetAttribute(gemm_mma_kernel<128, true, true>,
                         cudaFuncAttributeMaxDynamicSharedMemorySize, SMEM_128);
    cudaFuncSetAttribute(gemm_mma_kernel<64, true, true>,
                         cudaFuncAttributeMaxDynamicSharedMemorySize, SMEM_64);

    // degree + normalization + CSR (shared by all layers)
    deg_init_kernel<<<(N_NODES + 255) / 256, 256>>>();
    deg_count_kernel<<<(N_EDGES + 255) / 256, 256>>>(dst);
    dinv_kernel<<<(N_NODES + 255) / 256, 256>>>();
    alloc_kernel<<<(N_NODES + 255) / 256, 256>>>();
    fill_kernel<<<(N_EDGES + 255) / 256, 256>>>(src, dst);

    const int gemm_blocks = (N_NODES + 127) / 128;   // 391
    const int gather_blocks = (N_NODES + 7) / 8;     // 8 warps/block

    // Layer 1
    gemm_mma_kernel<128, false, false><<<gemm_blocks, 256, SMEM_128>>>(x, W1, N_NODES);
    gather_kernel<128, false><<<gather_blocks, 256>>>(b1, nullptr);

    // Layer 2
    gemm_mma_kernel<128, true, true><<<gemm_blocks, 256, SMEM_128>>>(nullptr, W2, N_NODES);
    gather_kernel<128, false><<<gather_blocks, 256>>>(b2, nullptr);

    // Layer 3 (N=64) -> d_out
    gemm_mma_kernel<64, true, true><<<gemm_blocks, 256, SMEM_64>>>(nullptr, W3, N_NODES);
    gather_kernel<64, true><<<gather_blocks, 256>>>(b3, out);
}